// round 2
// baseline (speedup 1.0000x reference)
#include <cuda_runtime.h>
#include <math.h>

#define N_NODES 20000
#define N_EDGES 320000
#define F_IN 512
#define HEADS 8
#define DHEAD 64
#define HD 512            // HEADS*DHEAD
#define ALPHA_SLOPE 0.2f
#define EPS_DEN 1e-16f

// ---------------- device scratch (static allocs only) ----------------
__device__ float g_he[N_NODES * HD];     // h_e, layout [n][h*64+d]
__device__ float g_hr[N_NODES * HD];     // h_r, layout [n][h*64+d]
__device__ float g_ssrc[N_NODES * HEADS];
__device__ float g_sdst[N_NODES * HEADS];
__device__ int   g_cnt[N_NODES];
__device__ int   g_off[N_NODES + 1];
__device__ int   g_cur[N_NODES];
__device__ int   g_sorted[N_EDGES];      // dst of edges sorted by src
__device__ int   g_is64;                 // 1 if edge_index is int64, 0 if int32

// ---------------- edge_index dtype detection ----------------
// If int64 (little-endian, values in [0, 20000)), the odd 32-bit words of the
// first 64 entries are all zero. For int32 data those words are real edge ids;
// P(all 32 sampled being zero) ~ (1/20000)^32 — negligible.
__global__ void detect_kernel(const int* __restrict__ ei32) {
    if (threadIdx.x == 0) {
        int odd_nonzero = 0;
        #pragma unroll 1
        for (int i = 0; i < 64; i++)
            odd_nonzero |= ei32[2 * i + 1];
        g_is64 = (odd_nonzero == 0) ? 1 : 0;
    }
}

__device__ __forceinline__ int load_edge(const void* ei, int idx) {
    // idx in [0, 2*E): flattened (2, E) array index
    int v;
    if (g_is64) v = (int)((const long long*)ei)[idx];
    else        v = ((const int*)ei)[idx];
    // defensive clamp: never crash on unexpected data
    v = v < 0 ? 0 : (v >= N_NODES ? N_NODES - 1 : v);
    return v;
}

// ---------------- sort-by-src: histogram ----------------
__global__ void zero_cnt_kernel() {
    int n = blockIdx.x * blockDim.x + threadIdx.x;
    if (n < N_NODES) g_cnt[n] = 0;
}

__global__ void hist_kernel(const void* __restrict__ ei) {
    int e = blockIdx.x * blockDim.x + threadIdx.x;
    if (e < N_EDGES) atomicAdd(&g_cnt[load_edge(ei, e)], 1);
}

// single-block exclusive scan over g_cnt -> g_off, g_cur; g_off[N]=E
__global__ void scan_kernel() {
    __shared__ int warp_sums[32];
    __shared__ int s_carry;
    int t = threadIdx.x;          // 1024 threads
    int lane = t & 31, wid = t >> 5;
    if (t == 0) s_carry = 0;
    __syncthreads();
    for (int base = 0; base < N_NODES; base += 1024) {
        int v = (base + t < N_NODES) ? g_cnt[base + t] : 0;
        int x = v;
        #pragma unroll
        for (int o = 1; o < 32; o <<= 1) {
            int y = __shfl_up_sync(0xffffffffu, x, o);
            if (lane >= o) x += y;
        }
        if (lane == 31) warp_sums[wid] = x;
        __syncthreads();
        if (wid == 0) {
            int ws = warp_sums[lane];
            #pragma unroll
            for (int o = 1; o < 32; o <<= 1) {
                int y = __shfl_up_sync(0xffffffffu, ws, o);
                if (lane >= o) ws += y;
            }
            warp_sums[lane] = ws;
        }
        __syncthreads();
        int incl = x + (wid > 0 ? warp_sums[wid - 1] : 0);
        int excl = s_carry + incl - v;
        if (base + t < N_NODES) { g_off[base + t] = excl; g_cur[base + t] = excl; }
        __syncthreads();
        if (t == 1023) s_carry += incl;
        __syncthreads();
    }
    if (t == 0) g_off[N_NODES] = s_carry;
}

__global__ void scatter_kernel(const void* __restrict__ ei) {
    int e = blockIdx.x * blockDim.x + threadIdx.x;
    if (e < N_EDGES) {
        int s = load_edge(ei, e);
        int d = load_edge(ei, N_EDGES + e);
        int p = atomicAdd(&g_cur[s], 1);
        if (p >= 0 && p < N_EDGES) g_sorted[p] = d;
    }
}

// ---------------- fp32 GEMM: C[n][h*64+d] = sum_f X[n][f] * W[h][f][d] ----------------
// grid: (ceil(N/128), 8 heads), block 256. Tile 128x64, BK=16.
__global__ __launch_bounds__(256, 2)
void gemm_kernel(const float* __restrict__ X, const float* __restrict__ W,
                 float* __restrict__ C) {
    __shared__ float As[16][132];   // [k][m], padded
    __shared__ float Bs[16][64];    // [k][n]
    int h = blockIdx.y;
    int n0 = blockIdx.x * 128;
    int tid = threadIdx.x;
    int tx = tid & 15;              // 16 col-groups of 4
    int ty = tid >> 4;              // 16 row-groups of 8
    const float* Wh = W + h * (F_IN * DHEAD);

    float c[8][4];
    #pragma unroll
    for (int i = 0; i < 8; i++)
        #pragma unroll
        for (int j = 0; j < 4; j++) c[i][j] = 0.f;

    for (int f0 = 0; f0 < F_IN; f0 += 16) {
        #pragma unroll
        for (int j = 0; j < 2; j++) {
            int idx = tid * 2 + j;          // 0..511
            int row = idx >> 2;
            int q = idx & 3;
            float4 v = make_float4(0.f, 0.f, 0.f, 0.f);
            if (n0 + row < N_NODES)
                v = *(const float4*)(X + (long)(n0 + row) * F_IN + f0 + q * 4);
            As[q * 4 + 0][row] = v.x;
            As[q * 4 + 1][row] = v.y;
            As[q * 4 + 2][row] = v.z;
            As[q * 4 + 3][row] = v.w;
        }
        {
            int fo = tid >> 4;
            int d4 = (tid & 15) * 4;
            float4 v = *(const float4*)(Wh + (f0 + fo) * DHEAD + d4);
            *(float4*)(&Bs[fo][d4]) = v;
        }
        __syncthreads();
        #pragma unroll
        for (int k = 0; k < 16; k++) {
            float4 a0 = *(const float4*)(&As[k][ty * 8]);
            float4 a1 = *(const float4*)(&As[k][ty * 8 + 4]);
            float4 b4 = *(const float4*)(&Bs[k][tx * 4]);
            float av[8] = {a0.x, a0.y, a0.z, a0.w, a1.x, a1.y, a1.z, a1.w};
            float bv[4] = {b4.x, b4.y, b4.z, b4.w};
            #pragma unroll
            for (int i = 0; i < 8; i++)
                #pragma unroll
                for (int j = 0; j < 4; j++)
                    c[i][j] = fmaf(av[i], bv[j], c[i][j]);
        }
        __syncthreads();
    }
    #pragma unroll
    for (int i = 0; i < 8; i++) {
        int row = n0 + ty * 8 + i;
        if (row < N_NODES) {
            float4 o4 = make_float4(c[i][0], c[i][1], c[i][2], c[i][3]);
            *(float4*)(C + (long)row * HD + h * DHEAD + tx * 4) = o4;
        }
    }
}

// ---------------- per-node attention-coefficient dots: ssrc/sdst ----------------
__global__ __launch_bounds__(128)
void s_kernel(const float* __restrict__ a) {
    int n = blockIdx.x;
    int t = threadIdx.x;
    int h = t >> 4;
    int l = t & 15;
    float4 he4 = *(const float4*)(g_he + (long)n * HD + t * 4);
    float4 as = *(const float4*)(a + h * 320 + 0 + l * 4);
    float4 ad = *(const float4*)(a + h * 320 + 64 + l * 4);
    float ps = he4.x * as.x + he4.y * as.y + he4.z * as.z + he4.w * as.w;
    float pd = he4.x * ad.x + he4.y * ad.y + he4.z * ad.z + he4.w * ad.w;
    #pragma unroll
    for (int o = 8; o > 0; o >>= 1) {
        ps += __shfl_xor_sync(0xffffffffu, ps, o);
        pd += __shfl_xor_sync(0xffffffffu, pd, o);
    }
    if (l == 0) {
        g_ssrc[n * HEADS + h] = ps;
        g_sdst[n * HEADS + h] = pd;
    }
}

// ---------------- per-node online-softmax attention + aggregation ----------------
// block 128 = one node (src). thread t: head h=t/16, dims 4(t&15)..
__global__ __launch_bounds__(128)
void attn_kernel(const float* __restrict__ a, float* __restrict__ out) {
    int n = blockIdx.x;
    int t = threadIdx.x;
    int h = t >> 4;
    int l = t & 15;

    int e0 = g_off[n];
    int e1 = g_off[n + 1];

    float4 hrs = *(const float4*)(g_hr + (long)n * HD + t * 4);
    float4 adif = *(const float4*)(a + h * 320 + 128 + l * 4);
    float4 aabs = *(const float4*)(a + h * 320 + 192 + l * 4);
    float4 aprd = *(const float4*)(a + h * 320 + 256 + l * 4);
    float ss = g_ssrc[n * HEADS + h];

    float m = -INFINITY;
    float denom = 0.f;
    float4 acc = make_float4(0.f, 0.f, 0.f, 0.f);

    int dst_next = (e0 < e1) ? g_sorted[e0] : 0;
    for (int i = e0; i < e1; i++) {
        int dst = dst_next;
        if (i + 1 < e1) dst_next = g_sorted[i + 1];

        float4 hrd = *(const float4*)(g_hr + (long)dst * HD + t * 4);
        float4 hed = *(const float4*)(g_he + (long)dst * HD + t * 4);

        float p;
        {
            float dx = hrd.x - hrs.x;
            float dy = hrd.y - hrs.y;
            float dz = hrd.z - hrs.z;
            float dw = hrd.w - hrs.w;
            p  = dx * adif.x + fabsf(dx) * aabs.x + hrs.x * hrd.x * aprd.x;
            p += dy * adif.y + fabsf(dy) * aabs.y + hrs.y * hrd.y * aprd.y;
            p += dz * adif.z + fabsf(dz) * aabs.z + hrs.z * hrd.z * aprd.z;
            p += dw * adif.w + fabsf(dw) * aabs.w + hrs.w * hrd.w * aprd.w;
        }
        #pragma unroll
        for (int o = 8; o > 0; o >>= 1) p += __shfl_xor_sync(0xffffffffu, p, o);

        float score = p + ss + g_sdst[dst * HEADS + h];
        float alpha = score > 0.f ? score : ALPHA_SLOPE * score;

        float newm = fmaxf(m, alpha);
        float scale = expf(m - newm);
        float pe = expf(alpha - newm);
        acc.x = acc.x * scale + pe * hed.x;
        acc.y = acc.y * scale + pe * hed.y;
        acc.z = acc.z * scale + pe * hed.z;
        acc.w = acc.w * scale + pe * hed.w;
        denom = denom * scale + pe;
        m = newm;
    }

    float inv = 1.f / (denom + EPS_DEN);
    float4 o4 = make_float4(acc.x * inv, acc.y * inv, acc.z * inv, acc.w * inv);
    *(float4*)(out + (long)n * HD + t * 4) = o4;
}

// ---------------- launch ----------------
extern "C" void kernel_launch(void* const* d_in, const int* in_sizes, int n_in,
                              void* d_out, int out_size) {
    const float* x = (const float*)d_in[0];
    const void* ei = d_in[1];
    const float* We = (const float*)d_in[2];
    const float* Wr = (const float*)d_in[3];
    const float* a = (const float*)d_in[4];
    float* out = (float*)d_out;

    float* he;  cudaGetSymbolAddress((void**)&he, g_he);
    float* hr;  cudaGetSymbolAddress((void**)&hr, g_hr);

    detect_kernel<<<1, 32>>>((const int*)ei);
    zero_cnt_kernel<<<(N_NODES + 255) / 256, 256>>>();
    hist_kernel<<<(N_EDGES + 255) / 256, 256>>>(ei);
    scan_kernel<<<1, 1024>>>();
    scatter_kernel<<<(N_EDGES + 255) / 256, 256>>>(ei);

    dim3 ggrid((N_NODES + 127) / 128, HEADS);
    gemm_kernel<<<ggrid, 256>>>(x, We, he);
    gemm_kernel<<<ggrid, 256>>>(x, Wr, hr);

    s_kernel<<<N_NODES, 128>>>(a);
    attn_kernel<<<N_NODES, 128>>>(a, out);
}

// round 3
// speedup vs baseline: 2.1855x; 2.1855x over previous
#include <cuda_runtime.h>
#include <math.h>
#include <stdint.h>

#define N_NODES 20000
#define N_EDGES 320000
#define F_IN 512
#define HEADS 8
#define DHEAD 64
#define HD 512
#define ALPHA_SLOPE 0.2f
#define EPS_DEN 1e-16f
#define NB_SCAN ((N_NODES + 255) / 256)   // 79

// ---------------- device scratch ----------------
__device__ float g_he[N_NODES * HD];
__device__ float g_hr[N_NODES * HD];
__device__ float g_xt[N_NODES * F_IN];          // tf32-rounded X
__device__ float g_wt[2 * HEADS * F_IN * DHEAD];// tf32-rounded We|Wr
__device__ float g_ssrc[N_NODES * HEADS];
__device__ float g_sdst[N_NODES * HEADS];
__device__ int   g_cnt[N_NODES];
__device__ int   g_off[N_NODES + 1];
__device__ int   g_cur[N_NODES];
__device__ int   g_sorted[N_EDGES];
__device__ int   g_bsum[NB_SCAN];
__device__ int   g_bpre[NB_SCAN];
__device__ int   g_is64;

// ---------------- edge dtype detection ----------------
__global__ void detect_kernel(const int* __restrict__ ei32) {
    if (threadIdx.x == 0) {
        int odd = 0;
        #pragma unroll 1
        for (int i = 0; i < 64; i++) odd |= ei32[2 * i + 1];
        g_is64 = (odd == 0) ? 1 : 0;
    }
}

__device__ __forceinline__ int load_edge(const void* ei, int idx) {
    int v;
    if (g_is64) v = (int)((const long long*)ei)[idx];
    else        v = ((const int*)ei)[idx];
    v = v < 0 ? 0 : (v >= N_NODES ? N_NODES - 1 : v);
    return v;
}

// ---------------- histogram ----------------
__global__ void zero_cnt_kernel() {
    int n = blockIdx.x * blockDim.x + threadIdx.x;
    if (n < N_NODES) g_cnt[n] = 0;
}

__global__ void hist_kernel(const void* __restrict__ ei) {
    int e = blockIdx.x * blockDim.x + threadIdx.x;
    if (e < N_EDGES) atomicAdd(&g_cnt[load_edge(ei, e)], 1);
}

// ---------------- 3-phase scan ----------------
__global__ void scan1_kernel() {      // NB_SCAN blocks x 256
    __shared__ int ws[8];
    int t = threadIdx.x, lane = t & 31, w = t >> 5;
    int idx = blockIdx.x * 256 + t;
    int v = (idx < N_NODES) ? g_cnt[idx] : 0;
    int x = v;
    #pragma unroll
    for (int o = 16; o > 0; o >>= 1) x += __shfl_xor_sync(0xffffffffu, x, o);
    if (lane == 0) ws[w] = x;
    __syncthreads();
    if (t == 0) {
        int s = 0;
        #pragma unroll
        for (int i = 0; i < 8; i++) s += ws[i];
        g_bsum[blockIdx.x] = s;
    }
}

__global__ void scan2_kernel() {      // 1 block x 128
    __shared__ int ws[4];
    int t = threadIdx.x, lane = t & 31, w = t >> 5;
    int v = (t < NB_SCAN) ? g_bsum[t] : 0;
    int x = v;
    #pragma unroll
    for (int o = 1; o < 32; o <<= 1) {
        int y = __shfl_up_sync(0xffffffffu, x, o);
        if (lane >= o) x += y;
    }
    if (lane == 31) ws[w] = x;
    __syncthreads();
    if (t == 0) {
        int s = 0;
        #pragma unroll
        for (int i = 0; i < 4; i++) { int tmp = ws[i]; ws[i] = s; s += tmp; }
    }
    __syncthreads();
    int incl = x + ws[w];
    if (t < NB_SCAN) g_bpre[t] = incl - v;
    if (t == NB_SCAN - 1) g_off[N_NODES] = incl;
}

__global__ void scan3_kernel() {      // NB_SCAN blocks x 256
    __shared__ int ws[8];
    int t = threadIdx.x, lane = t & 31, w = t >> 5;
    int idx = blockIdx.x * 256 + t;
    int v = (idx < N_NODES) ? g_cnt[idx] : 0;
    int x = v;
    #pragma unroll
    for (int o = 1; o < 32; o <<= 1) {
        int y = __shfl_up_sync(0xffffffffu, x, o);
        if (lane >= o) x += y;
    }
    if (lane == 31) ws[w] = x;
    __syncthreads();
    if (t == 0) {
        int s = 0;
        #pragma unroll
        for (int i = 0; i < 8; i++) { int tmp = ws[i]; ws[i] = s; s += tmp; }
    }
    __syncthreads();
    int excl = g_bpre[blockIdx.x] + ws[w] + x - v;
    if (idx < N_NODES) { g_off[idx] = excl; g_cur[idx] = excl; }
}

__global__ void scatter_kernel(const void* __restrict__ ei) {
    int e = blockIdx.x * blockDim.x + threadIdx.x;
    if (e < N_EDGES) {
        int s = load_edge(ei, e);
        int d = load_edge(ei, N_EDGES + e);
        int p = atomicAdd(&g_cur[s], 1);
        if (p >= 0 && p < N_EDGES) g_sorted[p] = d;
    }
}

// ---------------- tf32 rounding (RNA) ----------------
__device__ __forceinline__ float tf32_rna(float x) {
    uint32_t o;
    asm("cvt.rna.tf32.f32 %0, %1;" : "=r"(o) : "f"(x));
    return __uint_as_float(o);
}

__global__ void round_kernel(const float4* __restrict__ src, float4* __restrict__ dst, int n4) {
    int i = blockIdx.x * blockDim.x + threadIdx.x;
    if (i < n4) {
        float4 v = src[i];
        v.x = tf32_rna(v.x); v.y = tf32_rna(v.y);
        v.z = tf32_rna(v.z); v.w = tf32_rna(v.w);
        dst[i] = v;
    }
}

// ---------------- tf32 tensor-core GEMM ----------------
// C[n][h*64+d] = sum_f Xt[n][f] * Wt[mat][h][f][d]
// block tile 256x64, BK=32; 4 warps of 64x64 (mi 0..3 x ni 0..7)
#define BM 256
#define BK 32
#define A_STRIDE 36          // floats; bank(4r+k) conflict-free, 16B rows
#define B_STRIDE 72          // floats; bank(8k+c) conflict-free
#define A_FLOATS (BM * A_STRIDE)      // 9216
#define B_FLOATS (BK * B_STRIDE)      // 2304
#define BUF_FLOATS (A_FLOATS + B_FLOATS)

__device__ __forceinline__ void cp_async16(uint32_t saddr, const void* gaddr, int sz) {
    asm volatile("cp.async.cg.shared.global [%0], [%1], 16, %2;"
                 :: "r"(saddr), "l"(gaddr), "r"(sz));
}
__device__ __forceinline__ void cp_commit() {
    asm volatile("cp.async.commit_group;");
}

__global__ __launch_bounds__(128, 2)
void gemm_tf32_kernel() {
    extern __shared__ float sm[];
    int tid = threadIdx.x;
    int wid = tid >> 5;           // warp_m 0..3
    int lane = tid & 31;
    int g = lane >> 2;            // groupID
    int t4 = lane & 3;            // threadID_in_group

    int n0 = blockIdx.x * BM;
    int hy = blockIdx.y;          // 0..15
    int h = hy & 7;
    int mat = hy >> 3;

    const float* X = g_xt;
    const float* Wh = g_wt + (size_t)(mat * HEADS + h) * (F_IN * DHEAD);
    float* C = (mat == 0) ? g_he : g_hr;

    uint32_t sm_base = (uint32_t)__cvta_generic_to_shared(sm);

    float c[4][8][4];
    #pragma unroll
    for (int mi = 0; mi < 4; mi++)
        #pragma unroll
        for (int ni = 0; ni < 8; ni++)
            #pragma unroll
            for (int r = 0; r < 4; r++) c[mi][ni][r] = 0.f;

    // ---- async tile loader ----
    auto issue = [&](int buf, int f0) {
        uint32_t abase = sm_base + (uint32_t)(buf * BUF_FLOATS) * 4u;
        uint32_t bbase = abase + A_FLOATS * 4u;
        // A: 2048 float4, 16 per thread
        #pragma unroll
        for (int j = 0; j < 16; j++) {
            int linear = tid + j * 128;
            int row = linear >> 3;
            int kq = linear & 7;
            int grow = n0 + row;
            int pred = (grow < N_NODES) ? 16 : 0;
            int clamped = grow < N_NODES ? grow : (N_NODES - 1);
            const void* gp = X + (size_t)clamped * F_IN + f0 + kq * 4;
            uint32_t sp = abase + (uint32_t)(row * A_STRIDE + kq * 4) * 4u;
            cp_async16(sp, gp, pred);
        }
        // B: 512 float4, 4 per thread
        #pragma unroll
        for (int j = 0; j < 4; j++) {
            int linear = tid + j * 128;
            int k = linear >> 4;
            int c4 = (linear & 15) * 4;
            const void* gp = Wh + (size_t)(f0 + k) * DHEAD + c4;
            uint32_t sp = bbase + (uint32_t)(k * B_STRIDE + c4) * 4u;
            cp_async16(sp, gp, 16);
        }
        cp_commit();
    };

    const int TILES = F_IN / BK;   // 16
    issue(0, 0);

    for (int ti = 0; ti < TILES; ti++) {
        if (ti + 1 < TILES) {
            issue((ti + 1) & 1, (ti + 1) * BK);
            asm volatile("cp.async.wait_group 1;");
        } else {
            asm volatile("cp.async.wait_group 0;");
        }
        __syncthreads();

        const float* As = sm + (ti & 1) * BUF_FLOATS;
        const float* Bs = As + A_FLOATS;

        #pragma unroll
        for (int ks = 0; ks < 4; ks++) {
            int k0 = ks * 8;
            uint32_t a[4][4], b[8][2];
            #pragma unroll
            for (int mi = 0; mi < 4; mi++) {
                int r = wid * 64 + mi * 16 + g;
                a[mi][0] = __float_as_uint(As[r * A_STRIDE + k0 + t4]);
                a[mi][1] = __float_as_uint(As[(r + 8) * A_STRIDE + k0 + t4]);
                a[mi][2] = __float_as_uint(As[r * A_STRIDE + k0 + t4 + 4]);
                a[mi][3] = __float_as_uint(As[(r + 8) * A_STRIDE + k0 + t4 + 4]);
            }
            #pragma unroll
            for (int ni = 0; ni < 8; ni++) {
                int col = ni * 8 + g;
                b[ni][0] = __float_as_uint(Bs[(k0 + t4) * B_STRIDE + col]);
                b[ni][1] = __float_as_uint(Bs[(k0 + t4 + 4) * B_STRIDE + col]);
            }
            #pragma unroll
            for (int mi = 0; mi < 4; mi++)
                #pragma unroll
                for (int ni = 0; ni < 8; ni++) {
                    asm volatile(
                        "mma.sync.aligned.m16n8k8.row.col.f32.tf32.tf32.f32 "
                        "{%0,%1,%2,%3}, {%4,%5,%6,%7}, {%8,%9}, {%0,%1,%2,%3};"
                        : "+f"(c[mi][ni][0]), "+f"(c[mi][ni][1]),
                          "+f"(c[mi][ni][2]), "+f"(c[mi][ni][3])
                        : "r"(a[mi][0]), "r"(a[mi][1]), "r"(a[mi][2]), "r"(a[mi][3]),
                          "r"(b[ni][0]), "r"(b[ni][1]));
                }
        }
        __syncthreads();
    }

    // epilogue
    #pragma unroll
    for (int mi = 0; mi < 4; mi++) {
        int r0 = n0 + wid * 64 + mi * 16 + g;
        #pragma unroll
        for (int ni = 0; ni < 8; ni++) {
            int col = h * 64 + ni * 8 + 2 * t4;
            if (r0 < N_NODES)
                *(float2*)(C + (size_t)r0 * HD + col) = make_float2(c[mi][ni][0], c[mi][ni][1]);
            if (r0 + 8 < N_NODES)
                *(float2*)(C + (size_t)(r0 + 8) * HD + col) = make_float2(c[mi][ni][2], c[mi][ni][3]);
        }
    }
}

// ---------------- per-node coefficient dots ----------------
__global__ __launch_bounds__(128)
void s_kernel(const float* __restrict__ a) {
    int n = blockIdx.x;
    int t = threadIdx.x;
    int h = t >> 4;
    int l = t & 15;
    float4 he4 = *(const float4*)(g_he + (size_t)n * HD + t * 4);
    float4 as = *(const float4*)(a + h * 320 + 0 + l * 4);
    float4 ad = *(const float4*)(a + h * 320 + 64 + l * 4);
    float ps = he4.x * as.x + he4.y * as.y + he4.z * as.z + he4.w * as.w;
    float pd = he4.x * ad.x + he4.y * ad.y + he4.z * ad.z + he4.w * ad.w;
    #pragma unroll
    for (int o = 8; o > 0; o >>= 1) {
        ps += __shfl_xor_sync(0xffffffffu, ps, o);
        pd += __shfl_xor_sync(0xffffffffu, pd, o);
    }
    if (l == 0) {
        g_ssrc[n * HEADS + h] = ps;
        g_sdst[n * HEADS + h] = pd;
    }
}

// ---------------- online-softmax attention ----------------
__global__ __launch_bounds__(128)
void attn_kernel(const float* __restrict__ a, float* __restrict__ out) {
    int n = blockIdx.x;
    int t = threadIdx.x;
    int h = t >> 4;
    int l = t & 15;

    int e0 = g_off[n];
    int e1 = g_off[n + 1];

    float4 hrs = *(const float4*)(g_hr + (size_t)n * HD + t * 4);
    float4 adif = *(const float4*)(a + h * 320 + 128 + l * 4);
    float4 aabs = *(const float4*)(a + h * 320 + 192 + l * 4);
    float4 aprd = *(const float4*)(a + h * 320 + 256 + l * 4);
    float ss = g_ssrc[n * HEADS + h];

    float m = -INFINITY;
    float denom = 0.f;
    float4 acc = make_float4(0.f, 0.f, 0.f, 0.f);

    int dst_next = (e0 < e1) ? g_sorted[e0] : 0;
    for (int i = e0; i < e1; i++) {
        int dst = dst_next;
        if (i + 1 < e1) dst_next = g_sorted[i + 1];

        float4 hrd = *(const float4*)(g_hr + (size_t)dst * HD + t * 4);
        float4 hed = *(const float4*)(g_he + (size_t)dst * HD + t * 4);

        float p;
        {
            float dx = hrd.x - hrs.x;
            float dy = hrd.y - hrs.y;
            float dz = hrd.z - hrs.z;
            float dw = hrd.w - hrs.w;
            p  = dx * adif.x + fabsf(dx) * aabs.x + hrs.x * hrd.x * aprd.x;
            p += dy * adif.y + fabsf(dy) * aabs.y + hrs.y * hrd.y * aprd.y;
            p += dz * adif.z + fabsf(dz) * aabs.z + hrs.z * hrd.z * aprd.z;
            p += dw * adif.w + fabsf(dw) * aabs.w + hrs.w * hrd.w * aprd.w;
        }
        #pragma unroll
        for (int o = 8; o > 0; o >>= 1) p += __shfl_xor_sync(0xffffffffu, p, o);

        float score = p + ss + g_sdst[dst * HEADS + h];
        float alpha = score > 0.f ? score : ALPHA_SLOPE * score;

        float newm = fmaxf(m, alpha);
        float scale = __expf(m - newm);
        float pe = __expf(alpha - newm);
        acc.x = acc.x * scale + pe * hed.x;
        acc.y = acc.y * scale + pe * hed.y;
        acc.z = acc.z * scale + pe * hed.z;
        acc.w = acc.w * scale + pe * hed.w;
        denom = denom * scale + pe;
        m = newm;
    }

    float inv = 1.f / (denom + EPS_DEN);
    float4 o4 = make_float4(acc.x * inv, acc.y * inv, acc.z * inv, acc.w * inv);
    *(float4*)(out + (size_t)n * HD + t * 4) = o4;
}

// ---------------- launch ----------------
extern "C" void kernel_launch(void* const* d_in, const int* in_sizes, int n_in,
                              void* d_out, int out_size) {
    const float* x = (const float*)d_in[0];
    const void* ei = d_in[1];
    const float* We = (const float*)d_in[2];
    const float* Wr = (const float*)d_in[3];
    const float* a = (const float*)d_in[4];
    float* out = (float*)d_out;

    float* xt;  cudaGetSymbolAddress((void**)&xt, g_xt);
    float* wt;  cudaGetSymbolAddress((void**)&wt, g_wt);

    // edge prep
    detect_kernel<<<1, 32>>>((const int*)ei);
    zero_cnt_kernel<<<(N_NODES + 255) / 256, 256>>>();
    hist_kernel<<<(N_EDGES + 255) / 256, 256>>>(ei);
    scan1_kernel<<<NB_SCAN, 256>>>();
    scan2_kernel<<<1, 128>>>();
    scan3_kernel<<<NB_SCAN, 256>>>();
    scatter_kernel<<<(N_EDGES + 255) / 256, 256>>>(ei);

    // tf32 rounding
    {
        int n4x = N_NODES * F_IN / 4;
        round_kernel<<<(n4x + 255) / 256, 256>>>((const float4*)x, (float4*)xt, n4x);
        int n4w = HEADS * F_IN * DHEAD / 4;
        round_kernel<<<(n4w + 255) / 256, 256>>>((const float4*)We, (float4*)wt, n4w);
        round_kernel<<<(n4w + 255) / 256, 256>>>((const float4*)Wr, (float4*)(wt + HEADS * F_IN * DHEAD), n4w);
    }

    // GEMM
    static int smem_set = 0;
    size_t smem_bytes = 2 * BUF_FLOATS * sizeof(float);   // 92160
    cudaFuncSetAttribute(gemm_tf32_kernel, cudaFuncAttributeMaxDynamicSharedMemorySize, (int)smem_bytes);
    (void)smem_set;
    dim3 ggrid((N_NODES + BM - 1) / BM, 16);
    gemm_tf32_kernel<<<ggrid, 128, smem_bytes>>>();

    s_kernel<<<N_NODES, 128>>>(a);
    attn_kernel<<<N_NODES, 128>>>(a, out);
}